// round 7
// baseline (speedup 1.0000x reference)
#include <cuda_runtime.h>
#include <cuda_bf16.h>
#include <cstdint>

// Shapes fixed by the dataset reference:
//   y_true [B,T,K] f32 (exact one-hot), y_pred [B,T,K] f32, trans [K,K] f32
//   out [B] f32 = logsumexp(forward) - (point_score + trans_score)
static constexpr int B  = 64;
static constexpr int T  = 4096;
static constexpr int K  = 48;
static constexpr int CT = 256;      // timesteps per target-kernel chunk
static constexpr int CH = T / CT;   // 16 chunks

// Per-(batch, chunk) partial target scores. Every slot written every launch.
__device__ float g_part[B * CH];

// ---------------------------------------------------------------------------
// Kernel 1: target = point_score + trans_score, per (b, chunk).
// ---------------------------------------------------------------------------
__global__ void __launch_bounds__(CT) crf_target_kernel(
    const float* __restrict__ yt, const float* __restrict__ yp,
    const float* __restrict__ tr)
{
    const int b   = blockIdx.y;
    const int ch  = blockIdx.x;
    const int tid = threadIdx.x;

    __shared__ int   lab[CT + 1];
    __shared__ float pl [CT + 1];
    __shared__ int   mk [CT + 1];

    for (int i = tid; i <= CT; i += CT) { mk[i] = 1; lab[i] = 0; pl[i] = 0.0f; }
    __syncthreads();

    const int    t0   = ch * CT;
    const size_t base = ((size_t)b * T + t0) * K;
    const int lim = (t0 + CT >= T) ? (CT * K) : ((CT + 1) * K);

    for (int e = tid; e < lim; e += CT) {
        const float ypv = yp[base + e];
        const float ytv = yt[base + e];
        const int   t   = e / K;
        if (ypv <= -1000000.0f) mk[t] = 0;            // idempotent: race-safe
        if (ytv > 0.5f) { lab[t] = e - t * K; pl[t] = ypv; }
    }
    __syncthreads();

    float contrib = 0.0f;
    {
        const int t  = tid;
        const int gt = t0 + t;
        if (mk[t]) contrib = pl[t];
        if (gt + 1 < T && mk[t] && mk[t + 1])
            contrib += tr[lab[t] * K + lab[t + 1]];
    }

    #pragma unroll
    for (int o = 16; o > 0; o >>= 1)
        contrib += __shfl_down_sync(0xffffffffu, contrib, o);

    __shared__ float ws[CT / 32];
    if ((tid & 31) == 0) ws[tid >> 5] = contrib;
    __syncthreads();
    if (tid == 0) {
        float s = 0.0f;
        #pragma unroll
        for (int i = 0; i < CT / 32; i++) s += ws[i];
        g_part[b * CH + ch] = s;
    }
}

// ---------------------------------------------------------------------------
// f32x2 packed helpers (sm_103a)
// ---------------------------------------------------------------------------
__device__ __forceinline__ unsigned long long pk2(float lo, float hi) {
    unsigned long long r;
    asm("mov.b64 %0, {%1, %2};" : "=l"(r) : "f"(lo), "f"(hi));
    return r;
}
__device__ __forceinline__ void upk2(unsigned long long v, float& lo, float& hi) {
    asm("mov.b64 {%0, %1}, %2;" : "=f"(lo), "=f"(hi) : "l"(v));
}
__device__ __forceinline__ unsigned long long fma2_(unsigned long long a,
                                                    unsigned long long b,
                                                    unsigned long long c) {
    unsigned long long d;
    asm("fma.rn.f32x2 %0, %1, %2, %3;" : "=l"(d) : "l"(a), "l"(b), "l"(c));
    return d;
}
__device__ __forceinline__ unsigned long long add2_(unsigned long long a,
                                                    unsigned long long b) {
    unsigned long long d;
    asm("add.rn.f32x2 %0, %1, %2;" : "=l"(d) : "l"(a), "l"(b));
    return d;
}

// ---------------------------------------------------------------------------
// Kernel 2: forward scan, prob-domain. 2 warps per batch, one state per lane
// (48 active of 64). Rescale by W_0 only every 4th step (t % 4 == 0); between
// rescales ln(W) grows <= ~40, far inside f32 range.
//
// Per-step critical path: bar -> 12x LDS.128 -> 24x fma.rn.f32x2 -> add tree
// -> 1 FMUL -> SEL -> STS. Everything else (exp, mask votes, LDG refill,
// rcp/log on rescale steps) is pipelined ahead / overlapped with the dot.
// ---------------------------------------------------------------------------

// SL_N: vflag slot for t+1 (read into register for next step)
// SL_V: vflag slot for t+2 (this step's vote target)
// R:    rescale step (t % 4 == 0)
#define CRF_STEP(TT, P, SL_N, SL_V, QA, QN, QN2, QB, R) {                     \
    __syncthreads();                                                          \
    ulonglong2 wv[12];                                                        \
    _Pragma("unroll")                                                         \
    for (int c = 0; c < 12; c++) wv[c] = wb2[P][c];                           \
    unsigned long long d0 = 0ull, d1 = 0ull, d2 = 0ull, d3 = 0ull;            \
    _Pragma("unroll")                                                         \
    for (int c = 0; c < 12; c += 2) {                                         \
        d0 = fma2_(wv[c].x,     E2[2 * c],     d0);                           \
        d1 = fma2_(wv[c].y,     E2[2 * c + 1], d1);                           \
        d2 = fma2_(wv[c + 1].x, E2[2 * c + 2], d2);                           \
        d3 = fma2_(wv[c + 1].y, E2[2 * c + 3], d3);                           \
    }                                                                         \
    float scale, lw = 0.0f;                                                   \
    if (R) {                                                                  \
        float w0, wdm; upk2(wv[0].x, w0, wdm);                                \
        float rr; asm("rcp.approx.f32 %0, %1;" : "=f"(rr) : "f"(w0));         \
        lw = __logf(w0);                                                      \
        scale = fcur * rr;                                                    \
    } else {                                                                  \
        scale = fcur;                                                         \
    }                                                                         \
    const unsigned long long dd = add2_(add2_(d0, d1), add2_(d2, d3));        \
    float dx, dy; upk2(dd, dx, dy);                                           \
    const float wn = (dx + dy) * scale;                                       \
    if (mmcur) { wj = wn; if (R) C += lw; }                                   \
    if (act) wbufF[(P) ^ 1][j] = wj;                                          \
    /* future-step work, off the critical path: */                            \
    fcur  = __expf(QN);                                                       \
    mmcur = vflag[0][SL_N] & vflag[1][SL_N];                                  \
    { const int vn = __all_sync(0xffffffffu, (QN2) > -1000000.0f);            \
      if (l == 0) vflag[wd][SL_V] = vn; }                                     \
    QA = QB;                                                                  \
    { const int tn = (TT) + 8;                                                \
      QB = (tn < T) ? __ldg(xp + (size_t)tn * K) : 1e30f; }                   \
}

__global__ void __launch_bounds__(64, 1) crf_forward_kernel(
    const float* __restrict__ yp, const float* __restrict__ tr,
    float* __restrict__ out)
{
    const int  b   = blockIdx.x;
    const int  tid = threadIdx.x;
    const int  wd  = tid >> 5;              // warp id (0/1)
    const int  l   = tid & 31;              // lane
    const bool act = (l < 24);
    const int  j   = 24 * wd + (act ? l : 23);   // state owned by this lane

    __shared__ __align__(16) float wbufF[2][K];  // state, parity-buffered
    __shared__ int   vflag[2][4];                // [warp][t&3] mask votes
    __shared__ float redw[K];
    const ulonglong2 (*wb2)[12] = (const ulonglong2 (*)[12])wbufF;

    // E2[p] = (exp(trans[2p][j]), exp(trans[2p+1][j])) packed, registers.
    unsigned long long E2[K / 2];
    #pragma unroll
    for (int p = 0; p < K / 2; p++)
        E2[p] = pk2(__expf(tr[(2 * p) * K + j]),
                    __expf(tr[(2 * p + 1) * K + j]));

    const float* xp = yp + (size_t)b * T * K + j;

    // Prime: x0 (t=0), qA = t 1..4, qB = t 5..8.
    const float x0 = __ldg(xp);
    float qA0 = __ldg(xp + (size_t)1 * K), qA1 = __ldg(xp + (size_t)2 * K);
    float qA2 = __ldg(xp + (size_t)3 * K), qA3 = __ldg(xp + (size_t)4 * K);
    float qB0 = __ldg(xp + (size_t)5 * K), qB1 = __ldg(xp + (size_t)6 * K);
    float qB2 = __ldg(xp + (size_t)7 * K), qB3 = __ldg(xp + (size_t)8 * K);

    // Pre-loop votes: t=0 (slot 0), t=1 (slot 1), t=2 (slot 2).
    {
        const int v0 = __all_sync(0xffffffffu, x0  > -1000000.0f);
        const int v1 = __all_sync(0xffffffffu, qA0 > -1000000.0f);
        const int v2 = __all_sync(0xffffffffu, qA1 > -1000000.0f);
        if (l == 0) { vflag[wd][0] = v0; vflag[wd][1] = v1; vflag[wd][2] = v2; }
    }
    __syncthreads();

    const int m0 = vflag[0][0] & vflag[1][0];
    int  mmcur   = vflag[0][1] & vflag[1][1];     // mask for t=1, in register
    float fcur   = __expf(qA0);                   // exp(x_1), pipelined
    float wj = __expf(m0 ? x0 : 0.0f);            // W(0) = exp(s(0)), C(0)=0
    float C  = 0.0f;
    if (act) wbufF[1][j] = wj;                    // step t=1 reads parity 1

    // Steps t = 1..4095; parity = t&1; unroll 4, tb ≡ 1 (mod 4).
    // Slot schedule (t&3): k=0 reads slot2/votes slot3; k=1: 3/0; k=2: 0/1;
    // k=3 (t%4==0, RESCALE): 1/2.
    int tb = 1;
    for (; tb + 3 < T; tb += 4) {
        CRF_STEP(tb + 0, 1, 2, 3, qA0, qA1, qA2, qB0, false)
        CRF_STEP(tb + 1, 0, 3, 0, qA1, qA2, qA3, qB1, false)
        CRF_STEP(tb + 2, 1, 0, 1, qA2, qA3, qA0, qB2, false)
        CRF_STEP(tb + 3, 0, 1, 2, qA3, qA0, qA1, qB3, true)
    }
    // Tail: t = 4093, 4094, 4095 (none are rescale steps; W stays bounded).
    CRF_STEP(tb + 0, 1, 2, 3, qA0, qA1, qA2, qB0, false)
    CRF_STEP(tb + 1, 0, 3, 0, qA1, qA2, qA3, qB1, false)
    CRF_STEP(tb + 2, 1, 0, 1, qA2, qA3, qA0, qB2, false)

    // log_norm = C + log(sum_j W_j); subtract target. C is block-uniform.
    if (act) redw[j] = wj;
    __syncthreads();
    if (tid < 16) {
        float v = redw[tid] + redw[tid + 16] + redw[tid + 32];
        #pragma unroll
        for (int o = 8; o > 0; o >>= 1)
            v += __shfl_xor_sync(0x0000ffffu, v, o);
        if (tid == 0) {
            float tgt = 0.0f;
            #pragma unroll
            for (int i = 0; i < CH; i++) tgt += g_part[b * CH + i];
            out[b] = C + __logf(v) - tgt;
        }
    }
}

// ---------------------------------------------------------------------------
extern "C" void kernel_launch(void* const* d_in, const int* in_sizes, int n_in,
                              void* d_out, int out_size)
{
    const float* y_true = (const float*)d_in[0];
    const float* y_pred = (const float*)d_in[1];
    const float* trans  = (const float*)d_in[2];
    float* out = (float*)d_out;

    dim3 grid_t(CH, B);
    crf_target_kernel<<<grid_t, CT>>>(y_true, y_pred, trans);
    crf_forward_kernel<<<B, 64>>>(y_pred, trans, out);
}

// round 8
// speedup vs baseline: 4.8470x; 4.8470x over previous
#include <cuda_runtime.h>
#include <cuda_bf16.h>
#include <cstdint>

// Shapes fixed by the dataset reference:
//   y_true [B,T,K] f32 (exact one-hot), y_pred [B,T,K] f32, trans [K,K] f32
//   out [B] f32 = logsumexp(forward) - (point_score + trans_score)
static constexpr int B  = 64;
static constexpr int T  = 4096;
static constexpr int K  = 48;
static constexpr int CT = 256;      // timesteps per target-kernel chunk
static constexpr int CH = T / CT;   // 16 chunks (target kernel)

static constexpr int NC = 64;       // forward: number of scan chunks
static constexpr int GL = T / NC;   // 64 steps per chunk
static constexpr int GG = 32;       // guard steps (direction convergence)

// Scratch (written fully every launch: graph-replay safe).
__device__ float g_part [B * CH];   // target partials
__device__ float g_delta[B * NC];   // per-chunk log-norm increments

// ---------------------------------------------------------------------------
// Kernel 1: target = point_score + trans_score, per (b, chunk).
// ---------------------------------------------------------------------------
__global__ void __launch_bounds__(CT) crf_target_kernel(
    const float* __restrict__ yt, const float* __restrict__ yp,
    const float* __restrict__ tr)
{
    const int b   = blockIdx.y;
    const int ch  = blockIdx.x;
    const int tid = threadIdx.x;

    __shared__ int   lab[CT + 1];
    __shared__ float pl [CT + 1];
    __shared__ int   mk [CT + 1];

    for (int i = tid; i <= CT; i += CT) { mk[i] = 1; lab[i] = 0; pl[i] = 0.0f; }
    __syncthreads();

    const int    t0   = ch * CT;
    const size_t base = ((size_t)b * T + t0) * K;
    const int lim = (t0 + CT >= T) ? (CT * K) : ((CT + 1) * K);

    for (int e = tid; e < lim; e += CT) {
        const float ypv = yp[base + e];
        const float ytv = yt[base + e];
        const int   t   = e / K;
        if (ypv <= -1000000.0f) mk[t] = 0;            // idempotent: race-safe
        if (ytv > 0.5f) { lab[t] = e - t * K; pl[t] = ypv; }
    }
    __syncthreads();

    float contrib = 0.0f;
    {
        const int t  = tid;
        const int gt = t0 + t;
        if (mk[t]) contrib = pl[t];
        if (gt + 1 < T && mk[t] && mk[t + 1])
            contrib += tr[lab[t] * K + lab[t + 1]];
    }

    #pragma unroll
    for (int o = 16; o > 0; o >>= 1)
        contrib += __shfl_down_sync(0xffffffffu, contrib, o);

    __shared__ float ws[CT / 32];
    if ((tid & 31) == 0) ws[tid >> 5] = contrib;
    __syncthreads();
    if (tid == 0) {
        float s = 0.0f;
        #pragma unroll
        for (int i = 0; i < CT / 32; i++) s += ws[i];
        g_part[b * CH + ch] = s;
    }
}

// ---------------------------------------------------------------------------
// f32x2 packed helpers (sm_103a)
// ---------------------------------------------------------------------------
__device__ __forceinline__ unsigned long long pk2(float lo, float hi) {
    unsigned long long r;
    asm("mov.b64 %0, {%1, %2};" : "=l"(r) : "f"(lo), "f"(hi));
    return r;
}
__device__ __forceinline__ void upk2(unsigned long long v, float& lo, float& hi) {
    asm("mov.b64 {%0, %1}, %2;" : "=f"(lo), "=f"(hi) : "l"(v));
}
__device__ __forceinline__ unsigned long long fma2_(unsigned long long a,
                                                    unsigned long long b,
                                                    unsigned long long c) {
    unsigned long long d;
    asm("fma.rn.f32x2 %0, %1, %2, %3;" : "=l"(d) : "l"(a), "l"(b), "l"(c));
    return d;
}
__device__ __forceinline__ unsigned long long add2_(unsigned long long a,
                                                    unsigned long long b) {
    unsigned long long d;
    asm("add.rn.f32x2 %0, %1, %2;" : "=l"(d) : "l"(a), "l"(b));
    return d;
}

// ---------------------------------------------------------------------------
// Kernel 2: chunked forward scan, prob-domain, 2 warps per (batch, chunk).
// One state per lane (48 active of 64). Rescale by W_0 every 4th step.
//
// Chunk c > 0 starts GG=32 steps early from the uniform vector; Birkhoff
// contraction (tau ~ 0.37/step) makes the direction at the chunk boundary
// exact to ~1e-14. It reports D_c = [C+log sum W]_end - [C+log sum W]_boundary,
// which depends only on the boundary direction. Chunk 0 runs from the true
// init and reports its absolute end value. log_norm = sum over chunks.
// ---------------------------------------------------------------------------

#define CRF_STEP(TT, P, SL_N, SL_V, QA, QN, QN2, QB, R) {                     \
    __syncthreads();                                                          \
    ulonglong2 wv[12];                                                        \
    _Pragma("unroll")                                                         \
    for (int cc = 0; cc < 12; cc++) wv[cc] = wb2[P][cc];                      \
    unsigned long long d0 = 0ull, d1 = 0ull, d2 = 0ull, d3 = 0ull;            \
    _Pragma("unroll")                                                         \
    for (int cc = 0; cc < 12; cc += 2) {                                      \
        d0 = fma2_(wv[cc].x,     E2[2 * cc],     d0);                         \
        d1 = fma2_(wv[cc].y,     E2[2 * cc + 1], d1);                         \
        d2 = fma2_(wv[cc + 1].x, E2[2 * cc + 2], d2);                         \
        d3 = fma2_(wv[cc + 1].y, E2[2 * cc + 3], d3);                         \
    }                                                                         \
    float scale, lw = 0.0f;                                                   \
    if (R) {                                                                  \
        float w0, wdm; upk2(wv[0].x, w0, wdm);                                \
        float rr; asm("rcp.approx.f32 %0, %1;" : "=f"(rr) : "f"(w0));         \
        lw = __logf(w0);                                                      \
        scale = fcur * rr;                                                    \
    } else {                                                                  \
        scale = fcur;                                                         \
    }                                                                         \
    const unsigned long long dd = add2_(add2_(d0, d1), add2_(d2, d3));        \
    float dx, dy; upk2(dd, dx, dy);                                           \
    const float wn = (dx + dy) * scale;                                       \
    if (mmcur) { wj = wn; if (R) C += lw; }                                   \
    if (act) wbufF[(P) ^ 1][j] = wj;                                          \
    /* future-step work, off the critical path: */                            \
    fcur  = __expf(QN);                                                       \
    mmcur = vflag[0][SL_N] & vflag[1][SL_N];                                  \
    { const int vn = __all_sync(0xffffffffu, (QN2) > -1000000.0f);            \
      if (l == 0) vflag[wd][SL_V] = vn; }                                     \
    QA = QB;                                                                  \
    { int tn = (TT) + 8; tn = (tn > T - 1) ? (T - 1) : tn;                    \
      QB = __ldg(xp + (size_t)tn * K); }                                      \
}

#define CRF_GROUP(TB)                                                         \
    CRF_STEP((TB) + 0, 1, 2, 3, qA0, qA1, qA2, qB0, false)                    \
    CRF_STEP((TB) + 1, 0, 3, 0, qA1, qA2, qA3, qB1, false)                    \
    CRF_STEP((TB) + 2, 1, 0, 1, qA2, qA3, qA0, qB2, false)                    \
    CRF_STEP((TB) + 3, 0, 1, 2, qA3, qA0, qA1, qB3, true)

__global__ void __launch_bounds__(64, 8) crf_forward_kernel(
    const float* __restrict__ yp, const float* __restrict__ tr)
{
    const int  c   = blockIdx.x;            // chunk index 0..NC-1
    const int  b   = blockIdx.y;            // batch index
    const int  tid = threadIdx.x;
    const int  wd  = tid >> 5;              // warp id (0/1)
    const int  l   = tid & 31;              // lane
    const bool act = (l < 24);
    const int  j   = 24 * wd + (act ? l : 23);   // state owned by this lane

    __shared__ __align__(16) float wbufF[2][K];  // state, parity-buffered
    __shared__ int   vflag[2][4];                // [warp][t&3] mask votes
    __shared__ __align__(16) float redw[K];
    const ulonglong2 (*wb2)[12] = (const ulonglong2 (*)[12])wbufF;

    // E2[p] = (exp(trans[2p][j]), exp(trans[2p+1][j])) packed, registers.
    unsigned long long E2[K / 2];
    #pragma unroll
    for (int p = 0; p < K / 2; p++)
        E2[p] = pk2(__expf(tr[(2 * p) * K + j]),
                    __expf(tr[(2 * p + 1) * K + j]));

    const float* xp = yp + (size_t)b * T * K + j;

    // Chunk window: state times [tg, tend]; steps tg+1 .. tend.
    // tg == c*GL - GG (c>0) or 0 (c==0); tg % 4 == 0 always.
    const int tg   = (c == 0) ? 0 : c * GL - GG;
    const int tend = (c == NC - 1) ? (T - 1) : (c + 1) * GL;

    // Prefetch queues: qA = steps tg+1..tg+4, qB = tg+5..tg+8.
    float qA0 = __ldg(xp + (size_t)(tg + 1) * K);
    float qA1 = __ldg(xp + (size_t)(tg + 2) * K);
    float qA2 = __ldg(xp + (size_t)(tg + 3) * K);
    float qA3 = __ldg(xp + (size_t)(tg + 4) * K);
    float qB0 = __ldg(xp + (size_t)(tg + 5) * K);
    float qB1 = __ldg(xp + (size_t)(tg + 6) * K);
    float qB2 = __ldg(xp + (size_t)(tg + 7) * K);
    float qB3 = __ldg(xp + (size_t)(tg + 8) * K);

    // Init state.
    float wj, C = 0.0f;
    if (c == 0) {
        const float x0 = __ldg(xp);         // t = 0
        const int v0 = __all_sync(0xffffffffu, x0 > -1000000.0f);
        if (l == 0) vflag[wd][0] = v0;
    }
    // Prime votes: step tg+1 -> slot 1, step tg+2 -> slot 2.
    {
        const int v1 = __all_sync(0xffffffffu, qA0 > -1000000.0f);
        const int v2 = __all_sync(0xffffffffu, qA1 > -1000000.0f);
        if (l == 0) { vflag[wd][1] = v1; vflag[wd][2] = v2; }
    }
    __syncthreads();

    if (c == 0) {
        const int m0 = vflag[0][0] & vflag[1][0];
        wj = __expf(m0 ? __ldg(xp) : 0.0f);      // W(0)=exp(s(0))
    } else {
        wj = 1.0f;                                // uniform start (guard)
    }
    int   mmcur = vflag[0][1] & vflag[1][1];      // mask for first step
    float fcur  = __expf(qA0);                    // exp(x_{tg+1})
    if (act) wbufF[1][j] = wj;                    // first step reads parity 1

    int tb = tg + 1;

    // ---- Guard phase (c > 0): 8 groups = 32 steps, tg+1 .. c*GL ----
    if (c != 0) {
        for (int g = 0; g < GG / 4; g++) { CRF_GROUP(tb) tb += 4; }
    }

    // ---- Capture A_in = C + log(sum W) at the chunk boundary ----
    float A_in = 0.0f;
    if (c != 0) {
        __syncthreads();
        if (act) redw[j] = wj;
        __syncthreads();
        float s = 0.0f;
        #pragma unroll
        for (int i = 0; i < 12; i++) {
            const float4 v = ((const float4*)redw)[i];
            s += (v.x + v.y) + (v.z + v.w);
        }
        A_in = C + __logf(s);
    }

    // ---- Payload phase: 16 groups (chunk < NC-1 or c==0), else 15 + 3 ----
    const int ng = (c == NC - 1) ? (GL / 4 - 1) : (GL / 4);
    for (int g = 0; g < ng; g++) { CRF_GROUP(tb) tb += 4; }
    if (c == NC - 1) {
        CRF_STEP(tb + 0, 1, 2, 3, qA0, qA1, qA2, qB0, false)
        CRF_STEP(tb + 1, 0, 3, 0, qA1, qA2, qA3, qB1, false)
        CRF_STEP(tb + 2, 1, 0, 1, qA2, qA3, qA0, qB2, false)
    }
    (void)tend;

    // ---- A_out and per-chunk delta ----
    __syncthreads();
    if (act) redw[j] = wj;
    __syncthreads();
    if (tid == 0) {
        float s = 0.0f;
        #pragma unroll
        for (int i = 0; i < 12; i++) {
            const float4 v = ((const float4*)redw)[i];
            s += (v.x + v.y) + (v.z + v.w);
        }
        const float A_out = C + __logf(s);
        g_delta[b * NC + c] = A_out - A_in;     // A_in == 0 for c == 0
    }
}

// ---------------------------------------------------------------------------
// Kernel 3: out[b] = sum_c delta[b,c] - sum_i part[b,i]
// ---------------------------------------------------------------------------
__global__ void __launch_bounds__(64) crf_finalize_kernel(float* __restrict__ out)
{
    const int b   = blockIdx.x;
    const int tid = threadIdx.x;
    __shared__ float sd[NC];
    sd[tid] = g_delta[b * NC + tid];
    __syncthreads();
    if (tid == 0) {
        float s = 0.0f;
        #pragma unroll
        for (int i = 0; i < NC; i++) s += sd[i];
        float tgt = 0.0f;
        #pragma unroll
        for (int i = 0; i < CH; i++) tgt += g_part[b * CH + i];
        out[b] = s - tgt;
    }
}

// ---------------------------------------------------------------------------
extern "C" void kernel_launch(void* const* d_in, const int* in_sizes, int n_in,
                              void* d_out, int out_size)
{
    const float* y_true = (const float*)d_in[0];
    const float* y_pred = (const float*)d_in[1];
    const float* trans  = (const float*)d_in[2];
    float* out = (float*)d_out;

    dim3 grid_t(CH, B);
    crf_target_kernel<<<grid_t, CT>>>(y_true, y_pred, trans);
    dim3 grid_f(NC, B);
    crf_forward_kernel<<<grid_f, 64>>>(y_pred, trans);
    crf_finalize_kernel<<<B, 64>>>(out);
}

// round 10
// speedup vs baseline: 5.5936x; 1.1541x over previous
#include <cuda_runtime.h>
#include <cuda_bf16.h>
#include <cstdint>

// Shapes fixed by the dataset reference:
//   y_true [B,T,K] f32 (exact one-hot), y_pred [B,T,K] f32, trans [K,K] f32
//   out [B] f32 = logsumexp(forward) - (point_score + trans_score)
static constexpr int B  = 64;
static constexpr int T  = 4096;
static constexpr int K  = 48;

static constexpr int CT = 128;      // timesteps per target block
static constexpr int CH = T / CT;   // 32 target chunks per batch

static constexpr int NC = 64;       // forward scan chunks per batch
static constexpr int GL = T / NC;   // 64 payload steps per chunk
static constexpr int GG = 16;       // guard steps (Birkhoff convergence)

static constexpr int NFB = B * NC / 2;  // 2048 forward pair-blocks
static constexpr int NTB = B * CH;      // 2048 target blocks

// Scratch (fully rewritten every launch: graph-replay safe).
__device__ float g_part [B * CH];   // target partials
__device__ float g_delta[B * NC];   // per-chunk log-norm increments

// ---------------------------------------------------------------------------
// f32x2 packed helpers (sm_103a)
// ---------------------------------------------------------------------------
__device__ __forceinline__ unsigned long long pk2(float lo, float hi) {
    unsigned long long r;
    asm("mov.b64 %0, {%1, %2};" : "=l"(r) : "f"(lo), "f"(hi));
    return r;
}
__device__ __forceinline__ void upk2(unsigned long long v, float& lo, float& hi) {
    asm("mov.b64 {%0, %1}, %2;" : "=f"(lo), "=f"(hi) : "l"(v));
}
__device__ __forceinline__ unsigned long long fma2_(unsigned long long a,
                                                    unsigned long long b,
                                                    unsigned long long c) {
    unsigned long long d;
    asm("fma.rn.f32x2 %0, %1, %2, %3;" : "=l"(d) : "l"(a), "l"(b), "l"(c));
    return d;
}
__device__ __forceinline__ unsigned long long add2_(unsigned long long a,
                                                    unsigned long long b) {
    unsigned long long d;
    asm("add.rn.f32x2 %0, %1, %2;" : "=l"(d) : "l"(a), "l"(b));
    return d;
}

// Pair-scoped named barrier: 2 warps (64 threads), ids 1 and 2.
#define PBAR() asm volatile("bar.sync %0, 64;" :: "r"(pr + 1) : "memory")

// ---------------------------------------------------------------------------
// Forward step macro (prob-domain, lagged rescale every 4th step).
// Critical path: PBAR -> 12x LDS.128 -> 24x fma.rn.f32x2 -> add tree -> FMUL
// -> SEL -> STS. exp / votes / LDG refill pipelined ahead.
// ---------------------------------------------------------------------------
#define CRF_STEP(TT, P, SL_N, SL_V, QA, QN, QN2, QB, R) {                     \
    PBAR();                                                                   \
    ulonglong2 wv[12];                                                        \
    _Pragma("unroll")                                                         \
    for (int cc = 0; cc < 12; cc++) wv[cc] = wb2[P][cc];                      \
    unsigned long long d0 = 0ull, d1 = 0ull, d2 = 0ull, d3 = 0ull;            \
    _Pragma("unroll")                                                         \
    for (int cc = 0; cc < 12; cc += 2) {                                      \
        d0 = fma2_(wv[cc].x,     E2[2 * cc],     d0);                         \
        d1 = fma2_(wv[cc].y,     E2[2 * cc + 1], d1);                         \
        d2 = fma2_(wv[cc + 1].x, E2[2 * cc + 2], d2);                         \
        d3 = fma2_(wv[cc + 1].y, E2[2 * cc + 3], d3);                         \
    }                                                                         \
    float scale, lw = 0.0f;                                                   \
    if (R) {                                                                  \
        float w0, wdm; upk2(wv[0].x, w0, wdm);                                \
        float rr; asm("rcp.approx.f32 %0, %1;" : "=f"(rr) : "f"(w0));         \
        lw = __logf(w0);                                                      \
        scale = fcur * rr;                                                    \
    } else {                                                                  \
        scale = fcur;                                                         \
    }                                                                         \
    const unsigned long long dd = add2_(add2_(d0, d1), add2_(d2, d3));        \
    float dx, dy; upk2(dd, dx, dy);                                           \
    const float wn = (dx + dy) * scale;                                       \
    if (mmcur) { wj = wn; if (R) C += lw; }                                   \
    if (act) wbufP[(P) ^ 1][j] = wj;                                          \
    /* future-step work, off the critical path: */                            \
    fcur  = __expf(QN);                                                       \
    mmcur = vflagP[0][SL_N] & vflagP[1][SL_N];                                \
    { const int vn = __all_sync(0xffffffffu, (QN2) > -1000000.0f);            \
      if (l == 0) vflagP[wl][SL_V] = vn; }                                    \
    QA = QB;                                                                  \
    { int tn = (TT) + 8; tn = (tn > T - 1) ? (T - 1) : tn;                    \
      QB = __ldg(xp + (size_t)tn * K); }                                      \
}

#define CRF_GROUP(TB)                                                         \
    CRF_STEP((TB) + 0, 1, 2, 3, qA0, qA1, qA2, qB0, false)                    \
    CRF_STEP((TB) + 1, 0, 3, 0, qA1, qA2, qA3, qB1, false)                    \
    CRF_STEP((TB) + 2, 1, 0, 1, qA2, qA3, qA0, qB2, false)                    \
    CRF_STEP((TB) + 3, 0, 1, 2, qA3, qA0, qA1, qB3, true)

// ---------------------------------------------------------------------------
// Merged kernel: even blocks = forward chunk-pairs (2 warps per chunk, two
// independent pairs per block -> all 4 SMSPs used); odd blocks = target.
// ---------------------------------------------------------------------------
__global__ void __launch_bounds__(128, 4) crf_main_kernel(
    const float* __restrict__ yt, const float* __restrict__ yp,
    const float* __restrict__ tr)
{
    const int f   = blockIdx.x >> 1;
    const int tid = threadIdx.x;

    // Forward smem (per pair)
    __shared__ __align__(16) float wbufF[2][2][K];
    __shared__ int   vflag[2][2][4];
    __shared__ __align__(16) float redw[2][K];
    // Target smem
    __shared__ int   lab[CT + 1];
    __shared__ float pl [CT + 1];
    __shared__ int   mk [CT + 1];
    __shared__ float ws [4];

    if ((blockIdx.x & 1) == 0) {
        // =================== FORWARD PATH ===================
        const int  wid = tid >> 5;
        const int  pr  = wid >> 1;          // pair 0/1 -> chunk
        const int  wl  = wid & 1;           // warp-in-pair
        const int  l   = tid & 31;
        const bool act = (l < 24);
        const int  j   = 24 * wl + (act ? l : 23);

        const int g = f * 2 + pr;           // global chunk 0..4095
        const int b = g >> 6;
        const int c = g & (NC - 1);

        float (*wbufP)[K]  = wbufF[pr];
        int   (*vflagP)[4] = vflag[pr];
        float *redwP       = redw[pr];
        const ulonglong2 (*wb2)[12] = (const ulonglong2 (*)[12])wbufP;

        // E2[p] = (exp(trans[2p][j]), exp(trans[2p+1][j])), registers.
        unsigned long long E2[K / 2];
        #pragma unroll
        for (int p = 0; p < K / 2; p++)
            E2[p] = pk2(__expf(tr[(2 * p) * K + j]),
                        __expf(tr[(2 * p + 1) * K + j]));

        const float* xp = yp + (size_t)b * T * K + j;

        // Window: state times [tg, tend]; tg % 4 == 0.
        const int tg = (c == 0) ? 0 : c * GL - GG;

        float qA0 = __ldg(xp + (size_t)(tg + 1) * K);
        float qA1 = __ldg(xp + (size_t)(tg + 2) * K);
        float qA2 = __ldg(xp + (size_t)(tg + 3) * K);
        float qA3 = __ldg(xp + (size_t)(tg + 4) * K);
        float qB0 = __ldg(xp + (size_t)(tg + 5) * K);
        float qB1 = __ldg(xp + (size_t)(tg + 6) * K);
        float qB2 = __ldg(xp + (size_t)(tg + 7) * K);
        float qB3 = __ldg(xp + (size_t)(tg + 8) * K);

        float wj, C = 0.0f;
        if (c == 0) {
            const float x0 = __ldg(xp);
            const int v0 = __all_sync(0xffffffffu, x0 > -1000000.0f);
            if (l == 0) vflagP[wl][0] = v0;
        }
        {
            const int v1 = __all_sync(0xffffffffu, qA0 > -1000000.0f);
            const int v2 = __all_sync(0xffffffffu, qA1 > -1000000.0f);
            if (l == 0) { vflagP[wl][1] = v1; vflagP[wl][2] = v2; }
        }
        PBAR();

        if (c == 0) {
            const int m0 = vflagP[0][0] & vflagP[1][0];
            wj = __expf(m0 ? __ldg(xp) : 0.0f);
        } else {
            wj = 1.0f;                       // uniform start (guard)
        }
        int   mmcur = vflagP[0][1] & vflagP[1][1];
        float fcur  = __expf(qA0);
        if (act) wbufP[1][j] = wj;           // first step reads parity 1

        int tb = tg + 1;

        // Guard (c > 0): GG/4 = 4 groups.
        if (c != 0) {
            for (int gi = 0; gi < GG / 4; gi++) { CRF_GROUP(tb) tb += 4; }
        }

        // A_in at chunk boundary.
        float A_in = 0.0f;
        if (c != 0) {
            PBAR();
            if (act) redwP[j] = wj;
            PBAR();
            float s = 0.0f;
            #pragma unroll
            for (int i = 0; i < 12; i++) {
                const float4 v = ((const float4*)redwP)[i];
                s += (v.x + v.y) + (v.z + v.w);
            }
            A_in = C + __logf(s);
        }

        // Payload: 16 groups, except last chunk: 15 groups + 3 steps.
        const int ng = (c == NC - 1) ? (GL / 4 - 1) : (GL / 4);
        for (int gi = 0; gi < ng; gi++) { CRF_GROUP(tb) tb += 4; }
        if (c == NC - 1) {
            CRF_STEP(tb + 0, 1, 2, 3, qA0, qA1, qA2, qB0, false)
            CRF_STEP(tb + 1, 0, 3, 0, qA1, qA2, qA3, qB1, false)
            CRF_STEP(tb + 2, 1, 0, 1, qA2, qA3, qA0, qB2, false)
        }

        // A_out, per-chunk delta.
        PBAR();
        if (act) redwP[j] = wj;
        PBAR();
        if (tid == pr * 64) {
            float s = 0.0f;
            #pragma unroll
            for (int i = 0; i < 12; i++) {
                const float4 v = ((const float4*)redwP)[i];
                s += (v.x + v.y) + (v.z + v.w);
            }
            g_delta[b * NC + c] = (C + __logf(s)) - A_in;
        }
    } else {
        // =================== TARGET PATH ===================
        const int b  = f >> 5;               // 32 target chunks per batch
        const int ch = f & (CH - 1);

        for (int i = tid; i <= CT; i += 128) { mk[i] = 1; lab[i] = 0; pl[i] = 0.0f; }
        __syncthreads();

        const int    t0    = ch * CT;
        const size_t base4 = ((size_t)b * T + t0) * (K / 4);
        const float4* yp4  = (const float4*)yp + base4;
        const float4* yt4  = (const float4*)yt + base4;
        const int lim4 = ((ch == CH - 1) ? CT : (CT + 1)) * (K / 4);

        for (int v = tid; v < lim4; v += 128) {
            const float4 p = __ldg(yp4 + v);
            const float4 u = __ldg(yt4 + v);
            const int t = v / 12;
            if (p.x <= -1000000.0f || p.y <= -1000000.0f ||
                p.z <= -1000000.0f || p.w <= -1000000.0f) mk[t] = 0;
            const int cb = (v - t * 12) * 4;
            if (u.x > 0.5f) { lab[t] = cb;     pl[t] = p.x; }
            if (u.y > 0.5f) { lab[t] = cb + 1; pl[t] = p.y; }
            if (u.z > 0.5f) { lab[t] = cb + 2; pl[t] = p.z; }
            if (u.w > 0.5f) { lab[t] = cb + 3; pl[t] = p.w; }
        }
        __syncthreads();

        float contrib = 0.0f;
        {
            const int t  = tid;
            const int gt = t0 + t;
            if (t < CT && mk[t]) {
                contrib = pl[t];
                if (gt + 1 < T && mk[t + 1])
                    contrib += tr[lab[t] * K + lab[t + 1]];
            }
        }
        #pragma unroll
        for (int o = 16; o > 0; o >>= 1)
            contrib += __shfl_down_sync(0xffffffffu, contrib, o);
        if ((tid & 31) == 0) ws[tid >> 5] = contrib;
        __syncthreads();
        if (tid == 0)
            g_part[b * CH + ch] = (ws[0] + ws[1]) + (ws[2] + ws[3]);
    }
}

// ---------------------------------------------------------------------------
// Finalize: out[b] = sum_c delta[b,c] - sum_i part[b,i]
// ---------------------------------------------------------------------------
__global__ void __launch_bounds__(64) crf_finalize_kernel(float* __restrict__ out)
{
    const int b   = blockIdx.x;
    const int tid = threadIdx.x;
    float v = g_delta[b * NC + tid] - ((tid < CH) ? g_part[b * CH + tid] : 0.0f);
    #pragma unroll
    for (int o = 16; o > 0; o >>= 1)
        v += __shfl_down_sync(0xffffffffu, v, o);
    __shared__ float w2[2];
    if ((tid & 31) == 0) w2[tid >> 5] = v;
    __syncthreads();
    if (tid == 0) out[b] = w2[0] + w2[1];
}

// ---------------------------------------------------------------------------
extern "C" void kernel_launch(void* const* d_in, const int* in_sizes, int n_in,
                              void* d_out, int out_size)
{
    const float* y_true = (const float*)d_in[0];
    const float* y_pred = (const float*)d_in[1];
    const float* trans  = (const float*)d_in[2];
    float* out = (float*)d_out;

    crf_main_kernel<<<NFB + NTB, 128>>>(y_true, y_pred, trans);
    crf_finalize_kernel<<<B, 64>>>(out);
}